// round 15
// baseline (speedup 1.0000x reference)
#include <cuda_runtime.h>
#include <cuda_fp16.h>
#include <cuda_bf16.h>
#include <mma.h>
#include <cstdint>

using namespace nvcuda;

#define Bn 2
#define Cn 31
#define Dn 7
#define Hn 192
#define Wn 192
#define HWn (Hn * Wn)          // 36864
#define KP 70                  // KAN_PARAMS
#define COEF_LEN 56
#define NB 8                   // N_BASIS

// ---------------- scratch (no allocations allowed) ----------------
__device__ float  g_wts[Bn * KP * HWn];   // [B, 70, H, W]
__device__ __half g_wB[9 * 32 * 80];      // [kk][ci(pad32)][co(pad80)] fp16

// ---------------- kernel 0: one-time weight conversion ----------------
__global__ void wprep_kernel(const float* __restrict__ gw) {
    int idx = blockIdx.x * 256 + threadIdx.x;       // 9*32*80 = 23040
    if (idx >= 9 * 32 * 80) return;
    int kk = idx / 2560;
    int r  = idx - kk * 2560;
    int ci = r / 80;
    int co = r - ci * 80;
    float v = 0.f;
    if (ci < Cn && co < KP) v = gw[((size_t)co * Cn + ci) * 9 + kk];
    g_wB[idx] = __float2half(v);
}

// ---------------- kernel 2: conv with INLINE D-mean (9 shifted GEMMs, single wave) ----------------
// CTA = 3 image rows, 384 thr (12 warps), grid (64, 2) = 128 CTAs = one wave.
// Stage A computes mean over D=7 directly from windowed_x (no g_ctx round-trip);
// x is 64 MB and fits L2, so the 5/3 row-overlap re-reads are L2 hits.
#define LDA_A 40
#define SA_HALVES (5 * 208 * LDA_A)            // 41,600 -> 83,200 B
#define SB_OFF (SA_HALVES * 2)                 // 83,200
#define SB_HALVES (9 * 32 * 80)                // 23,040 -> 46,080 B
#define CONV_SMEM (SB_OFF + SB_HALVES * 2)     // 129,280 B

__global__ void __launch_bounds__(384, 1)
conv_wmma_kernel(const float* __restrict__ xin, const float* __restrict__ gb) {
    extern __shared__ char sm[];
    __half* sA = (__half*)sm;
    __half* sB = (__half*)(sm + SB_OFF);
    float*  sC = (float*)sm;                      // overlays sA after mainloop

    int tid = threadIdx.x;
    int wid = tid >> 5, lane = tid & 31;
    int y0 = blockIdx.x * 3;                      // first of 3 image rows
    int b  = blockIdx.y;

    // ---- stage B: u32 copy of pre-converted weights ----
    {
        const uint32_t* src = (const uint32_t*)g_wB;
        uint32_t* dst = (uint32_t*)sB;
#pragma unroll
        for (int i = 0; i < SB_HALVES / 2; i += 384)
            dst[i + tid] = src[i + tid];
    }

    // ---- stage A with inline mean over D: rows y0-1..y0+3, rx 0..207, 32 ci ----
    {
        const float* xb = xin + (size_t)b * Cn * Dn * HWn;
        int g = tid >> 5;                          // 0..11
#pragma unroll 1
        for (int s = 0; s < 14; s++) {
            int combo = s * 12 + g;                // 0..159 = (ry, ci)
            if (combo < 160) {
                int ry = combo >> 5;               // 0..4
                int ci = combo & 31;
                int gy = y0 - 1 + ry;
                bool rowok = (ci < Cn) && (gy >= 0) && (gy < Hn);
                const float* srow = xb + (size_t)ci * Dn * HWn + (size_t)gy * Wn;  // d=0 plane
                __half* drow = sA + (size_t)(ry * 208) * LDA_A + ci;
#pragma unroll
                for (int rseg = 0; rseg < 7; rseg++) {
                    int rx = rseg * 32 + lane;
                    if (rx < 208) {
                        int gx = rx - 1;
                        float sum = 0.f;
                        if (rowok && gx >= 0 && gx < Wn) {
#pragma unroll
                            for (int d = 0; d < Dn; d++)       // 7 independent LDGs
                                sum += srow[(size_t)d * HWn + gx];
                            sum *= (1.0f / 7.0f);
                        }
                        drow[(size_t)rx * LDA_A] = __float2half(sum);
                    }
                }
            }
        }
    }
    __syncthreads();

    // ---- mainloop: acc[3][5] ----
    wmma::fragment<wmma::accumulator, 16, 16, 16, float> acc[3][5];
#pragma unroll
    for (int mt = 0; mt < 3; mt++)
#pragma unroll
        for (int nt = 0; nt < 5; nt++) wmma::fill_fragment(acc[mt][nt], 0.f);

    int mbase = wid * 3;
#pragma unroll
    for (int kk = 0; kk < 9; kk++) {
        const int dy = kk / 3, dx = kk % 3;
#pragma unroll
        for (int ks = 0; ks < 2; ks++) {
            wmma::fragment<wmma::matrix_a, 16, 16, 16, __half, wmma::row_major> af[3];
#pragma unroll
            for (int mt = 0; mt < 3; mt++) {
                int m = mbase + mt;                 // 0..35
                int yr = m / 12;
                int xt = m - 12 * yr;
                int p0 = (yr + dy) * 208 + xt * 16 + dx;
                wmma::load_matrix_sync(af[mt], sA + (size_t)p0 * LDA_A + ks * 16, LDA_A);
            }
#pragma unroll
            for (int nt = 0; nt < 5; nt++) {
                wmma::fragment<wmma::matrix_b, 16, 16, 16, __half, wmma::row_major> bf;
                wmma::load_matrix_sync(bf, sB + kk * 2560 + ks * 16 * 80 + nt * 16, 80);
#pragma unroll
                for (int mt = 0; mt < 3; mt++)
                    wmma::mma_sync(acc[mt][nt], af[mt], bf, acc[mt][nt]);
            }
        }
    }

    __syncthreads();   // all warps done reading sA before sC overlays it

    // ---- epilogue ----
    float* sCw = sC + (size_t)wid * 16 * 84;
    float* outp = g_wts + (size_t)b * KP * HWn;
#pragma unroll
    for (int mt = 0; mt < 3; mt++) {
        int m = mbase + mt;
        int yr = m / 12;
        int xt = m - 12 * yr;
#pragma unroll
        for (int nt = 0; nt < 5; nt++)
            wmma::store_matrix_sync(sCw + nt * 16, acc[mt][nt], 84, wmma::mem_row_major);
        __syncwarp();
        int pix0 = (y0 + yr) * Wn + xt * 16;
        int px = lane & 15;
        int ch = lane >> 4;                        // 0/1
#pragma unroll 1
        for (int i = 0; i < 35; i++) {
            int co = i * 2 + ch;                   // 0..69
            outp[(size_t)co * HWn + pix0 + px] = sCw[(size_t)px * 84 + co] + __ldg(gb + co);
        }
        __syncwarp();
    }
}

// ---------------- kernel 3: kan — 3 independent accumulator chains (round-14 best) ----------------
#define KAN_SLOTS 99
#define KAN_SMEM_BYTES (KAN_SLOTS * 128 * 4)

__device__ __forceinline__ float tanh_approx(float v) {
    float r;
    asm("tanh.approx.f32 %0, %1;" : "=f"(r) : "f"(v));
    return r;
}

__global__ void __launch_bounds__(128, 4)
kan_kernel(const float* __restrict__ xin, float* __restrict__ out) {
    extern __shared__ float smem[];
    int tid = threadIdx.x;
    int b = blockIdx.y;
    int p = blockIdx.x * 128 + tid;

    float* col = smem + tid;                      // (slot s, px tid) at s*128 + tid
    const float* wbase = g_wts + (size_t)b * KP * HWn + p;

    float uw[Dn], rw[Dn];
#pragma unroll
    for (int d = 0; d < Dn; d++) {
        uw[d] = wbase[(size_t)(COEF_LEN + d) * HWn] * (1.0f / 6.0f);  // spline 1/6 folded
        rw[d] = wbase[(size_t)(COEF_LEN + Dn + d) * HWn];
    }

    // zero pads (slots 0-2, 11-13 per d; plus final slot 98)
#pragma unroll
    for (int d = 0; d < Dn; d++) {
        col[(d * 14 + 0) * 128]  = 0.f; col[(d * 14 + 1) * 128]  = 0.f; col[(d * 14 + 2) * 128]  = 0.f;
        col[(d * 14 + 11) * 128] = 0.f; col[(d * 14 + 12) * 128] = 0.f; col[(d * 14 + 13) * 128] = 0.f;
    }
    col[98 * 128] = 0.f;
    // coefficients premultiplied by uw[d]/6
#pragma unroll
    for (int k = 0; k < COEF_LEN; k++) {
        int d = k >> 3, g = k & 7;
        col[(d * 14 + 3 + g) * 128] = wbase[(size_t)k * HWn] * uw[d];
    }

    const float* xb = xin + (size_t)b * Cn * Dn * HWn + p;
    float* ob = out + (size_t)b * Cn * HWn + p;

#pragma unroll 1
    for (int c0 = 0; c0 < Cn; c0 += 4) {
        float xv[4][Dn];
#pragma unroll
        for (int cc = 0; cc < 4; cc++) {
            if (c0 + cc < Cn) {
#pragma unroll
                for (int d = 0; d < Dn; d++)
                    xv[cc][d] = xb[(size_t)((c0 + cc) * Dn + d) * HWn];
            }
        }
#pragma unroll
        for (int cc = 0; cc < 4; cc++) {
            if (c0 + cc < Cn) {
                float accA = 0.f, accB = 0.f, accR = 0.f;   // 3 independent chains
#pragma unroll
                for (int d = 0; d < Dn; d++) {
                    float x = xv[cc][d];
                    float xs = fmaf(x, 2.5f, 5.5f);
                    float jf = floorf(xs);
                    int j = (int)jf;
                    float t = xs - jf;
                    int jc = ((unsigned)j <= 10u) ? j : 11;   // clamp -> all-zero slots

                    float t2 = t * t;
                    float omt = 1.f - t;
                    float u0 = omt * omt * omt;
                    float u3 = t2 * t;
                    float u1 = fmaf(t2, fmaf(3.f, t, -6.f), 4.f);
                    float u2 = ((6.f - u0) - u1) - u3;        // partition of unity

                    const float* cf = col + (d * 14 + jc) * 128;
                    accA = fmaf(u0, cf[0],   accA);
                    accB = fmaf(u1, cf[128], accB);
                    accA = fmaf(u2, cf[256], accA);
                    accB = fmaf(u3, cf[384], accB);

                    // silu(x) = h + h*tanh(h), h = x/2
                    float h = 0.5f * x;
                    float th = tanh_approx(h);
                    float sl = fmaf(h, th, h);
                    accR = fmaf(sl, rw[d], accR);
                }
                ob[(size_t)(c0 + cc) * HWn] = (accA + accB) + accR;
            }
        }
    }
}

// ---------------- launch ----------------
extern "C" void kernel_launch(void* const* d_in, const int* in_sizes, int n_in,
                              void* d_out, int out_size) {
    const float* x  = (const float*)d_in[0];   // windowed_x [2,31,7,192,192]
    const float* gw = (const float*)d_in[1];   // gen_w [70,31,3,3]
    const float* gb = (const float*)d_in[2];   // gen_b [70]
    float* out = (float*)d_out;                // [2,31,192,192]

    cudaFuncSetAttribute(conv_wmma_kernel, cudaFuncAttributeMaxDynamicSharedMemorySize, CONV_SMEM);
    cudaFuncSetAttribute(kan_kernel,       cudaFuncAttributeMaxDynamicSharedMemorySize, KAN_SMEM_BYTES);

    wprep_kernel<<<90, 256>>>(gw);
    conv_wmma_kernel<<<dim3(Hn / 3, Bn), 384, CONV_SMEM>>>(x, gb);
    kan_kernel<<<dim3(HWn / 128, Bn), 128, KAN_SMEM_BYTES>>>(x, out);
}

// round 16
// speedup vs baseline: 1.2223x; 1.2223x over previous
#include <cuda_runtime.h>
#include <cuda_fp16.h>
#include <cuda_bf16.h>
#include <mma.h>
#include <cstdint>

using namespace nvcuda;

#define Bn 2
#define Cn 31
#define Dn 7
#define Hn 192
#define Wn 192
#define HWn (Hn * Wn)          // 36864
#define KP 70                  // KAN_PARAMS
#define COEF_LEN 56
#define NB 8                   // N_BASIS

// ---------------- scratch (no allocations allowed) ----------------
__device__ float  g_ctx[Bn * Cn * HWn];   // [B, C, H, W]
__device__ float  g_wts[Bn * KP * HWn];   // [B, 70, H, W]
__device__ __half g_wB[9 * 32 * 80];      // [kk][ci(pad32)][co(pad80)] fp16

// ---------------- kernel 1: mean over D (float4) + fused weight prep ----------------
__global__ void mean_kernel(const float* __restrict__ x, const float* __restrict__ gw) {
    int i = blockIdx.x * 256 + threadIdx.x;        // float4 index
    const int HW4 = HWn / 4;                       // 9216
    int hw4 = i % HW4;
    int bc  = i / HW4;
    const float4* p = (const float4*)(x + (size_t)bc * Dn * HWn) + hw4;
    float4 s = make_float4(0.f, 0.f, 0.f, 0.f);
#pragma unroll
    for (int d = 0; d < Dn; d++) {
        float4 v = p[(size_t)d * HW4];
        s.x += v.x; s.y += v.y; s.z += v.z; s.w += v.w;
    }
    const float inv7 = 1.0f / 7.0f;
    s.x *= inv7; s.y *= inv7; s.z *= inv7; s.w *= inv7;
    ((float4*)g_ctx)[i] = s;

    // fused one-time weight conversion (first 90 blocks cover 9*32*80 = 23040)
    if (i < 9 * 32 * 80) {
        int kk = i / 2560;
        int r  = i - kk * 2560;
        int ci = r / 80;
        int co = r - ci * 80;
        float v = 0.f;
        if (ci < Cn && co < KP) v = gw[((size_t)co * Cn + ci) * 9 + kk];
        g_wB[i] = __float2half(v);
    }
}

// ---------------- kernel 2: conv as 9 shifted GEMMs, single-wave (round-14 best) ----------------
#define LDA_A 40
#define SA_HALVES (5 * 208 * LDA_A)            // 41,600 -> 83,200 B
#define SB_OFF (SA_HALVES * 2)                 // 83,200
#define SB_HALVES (9 * 32 * 80)                // 23,040 -> 46,080 B
#define CONV_SMEM (SB_OFF + SB_HALVES * 2)     // 129,280 B

__global__ void __launch_bounds__(384, 1)
conv_wmma_kernel(const float* __restrict__ gb) {
    extern __shared__ char sm[];
    __half* sA = (__half*)sm;
    __half* sB = (__half*)(sm + SB_OFF);
    float*  sC = (float*)sm;                      // overlays sA after mainloop

    int tid = threadIdx.x;
    int wid = tid >> 5, lane = tid & 31;
    int y0 = blockIdx.x * 3;                      // first of 3 image rows
    int b  = blockIdx.y;

    // ---- stage B: u32 copy ----
    {
        const uint32_t* src = (const uint32_t*)g_wB;
        uint32_t* dst = (uint32_t*)sB;
#pragma unroll
        for (int i = 0; i < SB_HALVES / 2; i += 384)
            dst[i + tid] = src[i + tid];
    }

    // ---- stage A: ctx rows y0-1..y0+3 (5 rows), rx 0..207 (gx = rx-1), 32 ci ----
    {
        const float* ctx = g_ctx + (size_t)b * Cn * HWn;
        int g = tid >> 5;                          // 0..11
#pragma unroll 1
        for (int s = 0; s < 14; s++) {
            int combo = s * 12 + g;                // 0..159 = (ry, ci)
            if (combo < 160) {
                int ry = combo >> 5;               // 0..4
                int ci = combo & 31;
                int gy = y0 - 1 + ry;
                bool rowok = (ci < Cn) && (gy >= 0) && (gy < Hn);
                const float* srow = ctx + (size_t)ci * HWn + (size_t)gy * Wn;
                __half* drow = sA + (size_t)(ry * 208) * LDA_A + ci;
#pragma unroll
                for (int rseg = 0; rseg < 7; rseg++) {
                    int rx = rseg * 32 + lane;
                    if (rx < 208) {
                        int gx = rx - 1;
                        float v = (rowok && gx >= 0 && gx < Wn) ? srow[gx] : 0.f;
                        drow[(size_t)rx * LDA_A] = __float2half(v);
                    }
                }
            }
        }
    }
    __syncthreads();

    // ---- mainloop: acc[3][5] ----
    wmma::fragment<wmma::accumulator, 16, 16, 16, float> acc[3][5];
#pragma unroll
    for (int mt = 0; mt < 3; mt++)
#pragma unroll
        for (int nt = 0; nt < 5; nt++) wmma::fill_fragment(acc[mt][nt], 0.f);

    int mbase = wid * 3;
#pragma unroll
    for (int kk = 0; kk < 9; kk++) {
        const int dy = kk / 3, dx = kk % 3;
#pragma unroll
        for (int ks = 0; ks < 2; ks++) {
            wmma::fragment<wmma::matrix_a, 16, 16, 16, __half, wmma::row_major> af[3];
#pragma unroll
            for (int mt = 0; mt < 3; mt++) {
                int m = mbase + mt;                 // 0..35
                int yr = m / 12;
                int xt = m - 12 * yr;
                int p0 = (yr + dy) * 208 + xt * 16 + dx;
                wmma::load_matrix_sync(af[mt], sA + (size_t)p0 * LDA_A + ks * 16, LDA_A);
            }
#pragma unroll
            for (int nt = 0; nt < 5; nt++) {
                wmma::fragment<wmma::matrix_b, 16, 16, 16, __half, wmma::row_major> bf;
                wmma::load_matrix_sync(bf, sB + kk * 2560 + ks * 16 * 80 + nt * 16, 80);
#pragma unroll
                for (int mt = 0; mt < 3; mt++)
                    wmma::mma_sync(acc[mt][nt], af[mt], bf, acc[mt][nt]);
            }
        }
    }

    __syncthreads();   // all warps done reading sA before sC overlays it

    // ---- epilogue ----
    float* sCw = sC + (size_t)wid * 16 * 84;
    float* outp = g_wts + (size_t)b * KP * HWn;
#pragma unroll
    for (int mt = 0; mt < 3; mt++) {
        int m = mbase + mt;
        int yr = m / 12;
        int xt = m - 12 * yr;
#pragma unroll
        for (int nt = 0; nt < 5; nt++)
            wmma::store_matrix_sync(sCw + nt * 16, acc[mt][nt], 84, wmma::mem_row_major);
        __syncwarp();
        int pix0 = (y0 + yr) * Wn + xt * 16;
        int px = lane & 15;
        int ch = lane >> 4;                        // 0/1
#pragma unroll 1
        for (int i = 0; i < 35; i++) {
            int co = i * 2 + ch;                   // 0..69
            outp[(size_t)co * HWn + pix0 + px] = sCw[(size_t)px * 84 + co] + __ldg(gb + co);
        }
        __syncwarp();
    }
}

// ---------------- kernel 3: kan — batched 28-wide gather phase, then pure FMA phase ----------------
#define KAN_SLOTS 99
#define KAN_SMEM_BYTES (KAN_SLOTS * 128 * 4)

__device__ __forceinline__ float tanh_approx(float v) {
    float r;
    asm("tanh.approx.f32 %0, %1;" : "=f"(r) : "f"(v));
    return r;
}

__global__ void __launch_bounds__(128, 4)
kan_kernel(const float* __restrict__ xin, float* __restrict__ out) {
    extern __shared__ float smem[];
    int tid = threadIdx.x;
    int b = blockIdx.y;
    int p = blockIdx.x * 128 + tid;

    float* col = smem + tid;                      // (slot s, px tid) at s*128 + tid
    const float* wbase = g_wts + (size_t)b * KP * HWn + p;

    float uw[Dn], rw[Dn];
#pragma unroll
    for (int d = 0; d < Dn; d++) {
        uw[d] = wbase[(size_t)(COEF_LEN + d) * HWn] * (1.0f / 6.0f);  // spline 1/6 folded
        rw[d] = wbase[(size_t)(COEF_LEN + Dn + d) * HWn];
    }

    // zero pads (slots 0-2, 11-13 per d; plus final slot 98)
#pragma unroll
    for (int d = 0; d < Dn; d++) {
        col[(d * 14 + 0) * 128]  = 0.f; col[(d * 14 + 1) * 128]  = 0.f; col[(d * 14 + 2) * 128]  = 0.f;
        col[(d * 14 + 11) * 128] = 0.f; col[(d * 14 + 12) * 128] = 0.f; col[(d * 14 + 13) * 128] = 0.f;
    }
    col[98 * 128] = 0.f;
    // coefficients premultiplied by uw[d]/6
#pragma unroll
    for (int k = 0; k < COEF_LEN; k++) {
        int d = k >> 3, g = k & 7;
        col[(d * 14 + 3 + g) * 128] = wbase[(size_t)k * HWn] * uw[d];
    }

    const float* xb = xin + (size_t)b * Cn * Dn * HWn + p;
    float* ob = out + (size_t)b * Cn * HWn + p;

#pragma unroll 1
    for (int c0 = 0; c0 < Cn; c0 += 2) {
        // ---- batched x loads: up to 14 independent LDGs ----
        float xv[2][Dn];
#pragma unroll
        for (int cc = 0; cc < 2; cc++) {
            if (c0 + cc < Cn) {
#pragma unroll
                for (int d = 0; d < Dn; d++)
                    xv[cc][d] = xb[(size_t)((c0 + cc) * Dn + d) * HWn];
            }
        }
#pragma unroll
        for (int cc = 0; cc < 2; cc++) {
            if (c0 + cc < Cn) {
                // ---- phase 1: compute all intervals, issue all 28 gathers (MLP 28) ----
                float t[Dn];
                float cf0[Dn], cf1[Dn], cf2[Dn], cf3[Dn];
#pragma unroll
                for (int d = 0; d < Dn; d++) {
                    float x = xv[cc][d];
                    float xs = fmaf(x, 2.5f, 5.5f);
                    float jf = floorf(xs);
                    int j = (int)jf;
                    t[d] = xs - jf;
                    int jc = ((unsigned)j <= 10u) ? j : 11;   // clamp -> all-zero slots
                    const float* cf = col + (d * 14 + jc) * 128;
                    cf0[d] = cf[0];
                    cf1[d] = cf[128];
                    cf2[d] = cf[256];
                    cf3[d] = cf[384];
                }
                // ---- phase 2: pure register math ----
                float accA = 0.f, accB = 0.f, accR = 0.f;
#pragma unroll
                for (int d = 0; d < Dn; d++) {
                    float td = t[d];
                    float t2 = td * td;
                    float omt = 1.f - td;
                    float u0 = omt * omt * omt;
                    float u3 = t2 * td;
                    float u1 = fmaf(t2, fmaf(3.f, td, -6.f), 4.f);
                    float u2 = ((6.f - u0) - u1) - u3;        // partition of unity

                    accA = fmaf(u0, cf0[d], accA);
                    accB = fmaf(u1, cf1[d], accB);
                    accA = fmaf(u2, cf2[d], accA);
                    accB = fmaf(u3, cf3[d], accB);

                    // silu(x) = h + h*tanh(h), h = x/2
                    float h = 0.5f * xv[cc][d];
                    float th = tanh_approx(h);
                    float sl = fmaf(h, th, h);
                    accR = fmaf(sl, rw[d], accR);
                }
                ob[(size_t)(c0 + cc) * HWn] = (accA + accB) + accR;
            }
        }
    }
}

// ---------------- launch ----------------
extern "C" void kernel_launch(void* const* d_in, const int* in_sizes, int n_in,
                              void* d_out, int out_size) {
    const float* x  = (const float*)d_in[0];   // windowed_x [2,31,7,192,192]
    const float* gw = (const float*)d_in[1];   // gen_w [70,31,3,3]
    const float* gb = (const float*)d_in[2];   // gen_b [70]
    float* out = (float*)d_out;                // [2,31,192,192]

    cudaFuncSetAttribute(conv_wmma_kernel, cudaFuncAttributeMaxDynamicSharedMemorySize, CONV_SMEM);
    cudaFuncSetAttribute(kan_kernel,       cudaFuncAttributeMaxDynamicSharedMemorySize, KAN_SMEM_BYTES);

    mean_kernel<<<(Bn * Cn * HWn / 4) / 256, 256>>>(x, gw);
    conv_wmma_kernel<<<dim3(Hn / 3, Bn), 384, CONV_SMEM>>>(gb);
    kan_kernel<<<dim3(HWn / 128, Bn), 128, KAN_SMEM_BYTES>>>(x, out);
}

// round 17
// speedup vs baseline: 1.2453x; 1.0188x over previous
#include <cuda_runtime.h>
#include <cuda_fp16.h>
#include <cuda_bf16.h>
#include <mma.h>
#include <cstdint>

using namespace nvcuda;

#define Bn 2
#define Cn 31
#define Dn 7
#define Hn 192
#define Wn 192
#define HWn (Hn * Wn)          // 36864
#define KP 70                  // KAN_PARAMS
#define COEF_LEN 56
#define NB 8                   // N_BASIS

// ---------------- scratch (no allocations allowed) ----------------
__device__ float  g_ctx[Bn * Cn * HWn];   // [B, C, H, W]
__device__ float  g_wts[Bn * KP * HWn];   // [B, 70, H, W]
__device__ __half g_wB[9 * 32 * 80];      // [kk][ci(pad32)][co(pad80)] fp16

// ---------------- kernel 1: mean over D + fused weight prep ----------------
// Each thread processes TWO far-apart float4s (i and i + NHALF): same coalescing,
// double MLP (7 -> 14 independent LDG.128) to push DRAM% up.
#define N4 (Bn * Cn * HWn / 4)      // 571,392 float4
#define NHALF (N4 / 2)              // 285,696

__global__ void mean_kernel(const float* __restrict__ x, const float* __restrict__ gw) {
    const int HW4 = HWn / 4;                       // 9216
    int i0 = blockIdx.x * 256 + threadIdx.x;       // 0..NHALF-1
#pragma unroll
    for (int u = 0; u < 2; u++) {
        int i = i0 + u * NHALF;
        int hw4 = i % HW4;
        int bc  = i / HW4;
        const float4* p = (const float4*)(x + (size_t)bc * Dn * HWn) + hw4;
        float4 s = make_float4(0.f, 0.f, 0.f, 0.f);
#pragma unroll
        for (int d = 0; d < Dn; d++) {
            float4 v = p[(size_t)d * HW4];
            s.x += v.x; s.y += v.y; s.z += v.z; s.w += v.w;
        }
        const float inv7 = 1.0f / 7.0f;
        s.x *= inv7; s.y *= inv7; s.z *= inv7; s.w *= inv7;
        ((float4*)g_ctx)[i] = s;
    }

    // fused one-time weight conversion (first 90 blocks cover 9*32*80 = 23040)
    if (i0 < 9 * 32 * 80) {
        int kk = i0 / 2560;
        int r  = i0 - kk * 2560;
        int ci = r / 80;
        int co = r - ci * 80;
        float v = 0.f;
        if (ci < Cn && co < KP) v = gw[((size_t)co * Cn + ci) * 9 + kk];
        g_wB[i0] = __float2half(v);
    }
}

// ---------------- kernel 2: conv as 9 shifted GEMMs, single-wave (round-14 best) ----------------
#define LDA_A 40
#define SA_HALVES (5 * 208 * LDA_A)            // 41,600 -> 83,200 B
#define SB_OFF (SA_HALVES * 2)                 // 83,200
#define SB_HALVES (9 * 32 * 80)                // 23,040 -> 46,080 B
#define CONV_SMEM (SB_OFF + SB_HALVES * 2)     // 129,280 B

__global__ void __launch_bounds__(384, 1)
conv_wmma_kernel(const float* __restrict__ gb) {
    extern __shared__ char sm[];
    __half* sA = (__half*)sm;
    __half* sB = (__half*)(sm + SB_OFF);
    float*  sC = (float*)sm;                      // overlays sA after mainloop

    int tid = threadIdx.x;
    int wid = tid >> 5, lane = tid & 31;
    int y0 = blockIdx.x * 3;                      // first of 3 image rows
    int b  = blockIdx.y;

    // ---- stage B: u32 copy ----
    {
        const uint32_t* src = (const uint32_t*)g_wB;
        uint32_t* dst = (uint32_t*)sB;
#pragma unroll
        for (int i = 0; i < SB_HALVES / 2; i += 384)
            dst[i + tid] = src[i + tid];
    }

    // ---- stage A: ctx rows y0-1..y0+3 (5 rows), rx 0..207 (gx = rx-1), 32 ci ----
    {
        const float* ctx = g_ctx + (size_t)b * Cn * HWn;
        int g = tid >> 5;                          // 0..11
#pragma unroll 1
        for (int s = 0; s < 14; s++) {
            int combo = s * 12 + g;                // 0..159 = (ry, ci)
            if (combo < 160) {
                int ry = combo >> 5;               // 0..4
                int ci = combo & 31;
                int gy = y0 - 1 + ry;
                bool rowok = (ci < Cn) && (gy >= 0) && (gy < Hn);
                const float* srow = ctx + (size_t)ci * HWn + (size_t)gy * Wn;
                __half* drow = sA + (size_t)(ry * 208) * LDA_A + ci;
#pragma unroll
                for (int rseg = 0; rseg < 7; rseg++) {
                    int rx = rseg * 32 + lane;
                    if (rx < 208) {
                        int gx = rx - 1;
                        float v = (rowok && gx >= 0 && gx < Wn) ? srow[gx] : 0.f;
                        drow[(size_t)rx * LDA_A] = __float2half(v);
                    }
                }
            }
        }
    }
    __syncthreads();

    // ---- mainloop: acc[3][5] ----
    wmma::fragment<wmma::accumulator, 16, 16, 16, float> acc[3][5];
#pragma unroll
    for (int mt = 0; mt < 3; mt++)
#pragma unroll
        for (int nt = 0; nt < 5; nt++) wmma::fill_fragment(acc[mt][nt], 0.f);

    int mbase = wid * 3;
#pragma unroll
    for (int kk = 0; kk < 9; kk++) {
        const int dy = kk / 3, dx = kk % 3;
#pragma unroll
        for (int ks = 0; ks < 2; ks++) {
            wmma::fragment<wmma::matrix_a, 16, 16, 16, __half, wmma::row_major> af[3];
#pragma unroll
            for (int mt = 0; mt < 3; mt++) {
                int m = mbase + mt;                 // 0..35
                int yr = m / 12;
                int xt = m - 12 * yr;
                int p0 = (yr + dy) * 208 + xt * 16 + dx;
                wmma::load_matrix_sync(af[mt], sA + (size_t)p0 * LDA_A + ks * 16, LDA_A);
            }
#pragma unroll
            for (int nt = 0; nt < 5; nt++) {
                wmma::fragment<wmma::matrix_b, 16, 16, 16, __half, wmma::row_major> bf;
                wmma::load_matrix_sync(bf, sB + kk * 2560 + ks * 16 * 80 + nt * 16, 80);
#pragma unroll
                for (int mt = 0; mt < 3; mt++)
                    wmma::mma_sync(acc[mt][nt], af[mt], bf, acc[mt][nt]);
            }
        }
    }

    __syncthreads();   // all warps done reading sA before sC overlays it

    // ---- epilogue ----
    float* sCw = sC + (size_t)wid * 16 * 84;
    float* outp = g_wts + (size_t)b * KP * HWn;
#pragma unroll
    for (int mt = 0; mt < 3; mt++) {
        int m = mbase + mt;
        int yr = m / 12;
        int xt = m - 12 * yr;
#pragma unroll
        for (int nt = 0; nt < 5; nt++)
            wmma::store_matrix_sync(sCw + nt * 16, acc[mt][nt], 84, wmma::mem_row_major);
        __syncwarp();
        int pix0 = (y0 + yr) * Wn + xt * 16;
        int px = lane & 15;
        int ch = lane >> 4;                        // 0/1
#pragma unroll 1
        for (int i = 0; i < 35; i++) {
            int co = i * 2 + ch;                   // 0..69
            outp[(size_t)co * HWn + pix0 + px] = sCw[(size_t)px * 84 + co] + __ldg(gb + co);
        }
        __syncwarp();
    }
}

// ---------------- kernel 3: kan — round-14 best (4-ch batch, 3 chains, tanh silu) ----------------
#define KAN_SLOTS 99
#define KAN_SMEM_BYTES (KAN_SLOTS * 128 * 4)

__device__ __forceinline__ float tanh_approx(float v) {
    float r;
    asm("tanh.approx.f32 %0, %1;" : "=f"(r) : "f"(v));
    return r;
}

__global__ void __launch_bounds__(128, 4)
kan_kernel(const float* __restrict__ xin, float* __restrict__ out) {
    extern __shared__ float smem[];
    int tid = threadIdx.x;
    int b = blockIdx.y;
    int p = blockIdx.x * 128 + tid;

    float* col = smem + tid;                      // (slot s, px tid) at s*128 + tid
    const float* wbase = g_wts + (size_t)b * KP * HWn + p;

    float uw[Dn], rw[Dn];
#pragma unroll
    for (int d = 0; d < Dn; d++) {
        uw[d] = wbase[(size_t)(COEF_LEN + d) * HWn] * (1.0f / 6.0f);  // spline 1/6 folded
        rw[d] = wbase[(size_t)(COEF_LEN + Dn + d) * HWn];
    }

    // zero pads (slots 0-2, 11-13 per d; plus final slot 98)
#pragma unroll
    for (int d = 0; d < Dn; d++) {
        col[(d * 14 + 0) * 128]  = 0.f; col[(d * 14 + 1) * 128]  = 0.f; col[(d * 14 + 2) * 128]  = 0.f;
        col[(d * 14 + 11) * 128] = 0.f; col[(d * 14 + 12) * 128] = 0.f; col[(d * 14 + 13) * 128] = 0.f;
    }
    col[98 * 128] = 0.f;
    // coefficients premultiplied by uw[d]/6
#pragma unroll
    for (int k = 0; k < COEF_LEN; k++) {
        int d = k >> 3, g = k & 7;
        col[(d * 14 + 3 + g) * 128] = wbase[(size_t)k * HWn] * uw[d];
    }

    const float* xb = xin + (size_t)b * Cn * Dn * HWn + p;
    float* ob = out + (size_t)b * Cn * HWn + p;

#pragma unroll 1
    for (int c0 = 0; c0 < Cn; c0 += 4) {
        float xv[4][Dn];
#pragma unroll
        for (int cc = 0; cc < 4; cc++) {
            if (c0 + cc < Cn) {
#pragma unroll
                for (int d = 0; d < Dn; d++)
                    xv[cc][d] = xb[(size_t)((c0 + cc) * Dn + d) * HWn];
            }
        }
#pragma unroll
        for (int cc = 0; cc < 4; cc++) {
            if (c0 + cc < Cn) {
                float accA = 0.f, accB = 0.f, accR = 0.f;   // 3 independent chains
#pragma unroll
                for (int d = 0; d < Dn; d++) {
                    float x = xv[cc][d];
                    float xs = fmaf(x, 2.5f, 5.5f);
                    float jf = floorf(xs);
                    int j = (int)jf;
                    float t = xs - jf;
                    int jc = ((unsigned)j <= 10u) ? j : 11;   // clamp -> all-zero slots

                    float t2 = t * t;
                    float omt = 1.f - t;
                    float u0 = omt * omt * omt;
                    float u3 = t2 * t;
                    float u1 = fmaf(t2, fmaf(3.f, t, -6.f), 4.f);
                    float u2 = ((6.f - u0) - u1) - u3;        // partition of unity

                    const float* cf = col + (d * 14 + jc) * 128;
                    accA = fmaf(u0, cf[0],   accA);
                    accB = fmaf(u1, cf[128], accB);
                    accA = fmaf(u2, cf[256], accA);
                    accB = fmaf(u3, cf[384], accB);

                    // silu(x) = h + h*tanh(h), h = x/2
                    float h = 0.5f * x;
                    float th = tanh_approx(h);
                    float sl = fmaf(h, th, h);
                    accR = fmaf(sl, rw[d], accR);
                }
                ob[(size_t)(c0 + cc) * HWn] = (accA + accB) + accR;
            }
        }
    }
}

// ---------------- launch ----------------
extern "C" void kernel_launch(void* const* d_in, const int* in_sizes, int n_in,
                              void* d_out, int out_size) {
    const float* x  = (const float*)d_in[0];   // windowed_x [2,31,7,192,192]
    const float* gw = (const float*)d_in[1];   // gen_w [70,31,3,3]
    const float* gb = (const float*)d_in[2];   // gen_b [70]
    float* out = (float*)d_out;                // [2,31,192,192]

    cudaFuncSetAttribute(conv_wmma_kernel, cudaFuncAttributeMaxDynamicSharedMemorySize, CONV_SMEM);
    cudaFuncSetAttribute(kan_kernel,       cudaFuncAttributeMaxDynamicSharedMemorySize, KAN_SMEM_BYTES);

    mean_kernel<<<NHALF / 256, 256>>>(x, gw);
    conv_wmma_kernel<<<dim3(Hn / 3, Bn), 384, CONV_SMEM>>>(gb);
    kan_kernel<<<dim3(HWn / 128, Bn), 128, KAN_SMEM_BYTES>>>(x, out);
}